// round 1
// baseline (speedup 1.0000x reference)
#include <cuda_runtime.h>
#include <math.h>

#define SDIM 2048
#define HDIM 1024
#define BATCH 4

// Scratch: __device__ globals (no allocations allowed)
__device__ float g_probs [BATCH * SDIM * SDIM];  // 64 MB
__device__ float g_values[BATCH * SDIM * HDIM];  // 32 MB
__device__ float g_out1  [BATCH * SDIM * HDIM];  // 32 MB

// ---------------------------------------------------------------------------
// Softmax over rows of (R + mask[b,0]) -> probs[b, q, :]
// One block per (b, q) row. 256 threads, 8 elements/thread in registers.
// ---------------------------------------------------------------------------
__global__ __launch_bounds__(256) void softmax_kernel(
    const float* __restrict__ R, const float* __restrict__ mask,
    float* __restrict__ probs)
{
    const int row = blockIdx.x;            // 0 .. BATCH*SDIM-1
    const int b = row / SDIM;
    const int q = row % SDIM;
    const int t = threadIdx.x;

    const float* rrow = R + (size_t)q * SDIM;
    const float* mrow = mask + ((size_t)b * SDIM + q) * SDIM;

    float v[8];
    float4 r0 = *(const float4*)(rrow + t * 4);
    float4 m0 = *(const float4*)(mrow + t * 4);
    float4 r1 = *(const float4*)(rrow + 1024 + t * 4);
    float4 m1 = *(const float4*)(mrow + 1024 + t * 4);
    v[0] = r0.x + m0.x; v[1] = r0.y + m0.y; v[2] = r0.z + m0.z; v[3] = r0.w + m0.w;
    v[4] = r1.x + m1.x; v[5] = r1.y + m1.y; v[6] = r1.z + m1.z; v[7] = r1.w + m1.w;

    float mx = v[0];
    #pragma unroll
    for (int i = 1; i < 8; i++) mx = fmaxf(mx, v[i]);
    #pragma unroll
    for (int o = 16; o > 0; o >>= 1) mx = fmaxf(mx, __shfl_xor_sync(0xffffffffu, mx, o));

    __shared__ float smx[8];
    __shared__ float ssum[8];
    const int wid = t >> 5, lid = t & 31;
    if (lid == 0) smx[wid] = mx;
    __syncthreads();
    if (wid == 0) {
        float m = (lid < 8) ? smx[lid] : -INFINITY;
        #pragma unroll
        for (int o = 4; o > 0; o >>= 1) m = fmaxf(m, __shfl_xor_sync(0xffffffffu, m, o));
        if (lid == 0) smx[0] = m;
    }
    __syncthreads();
    mx = smx[0];

    float sum = 0.f;
    #pragma unroll
    for (int i = 0; i < 8; i++) { v[i] = __expf(v[i] - mx); sum += v[i]; }
    #pragma unroll
    for (int o = 16; o > 0; o >>= 1) sum += __shfl_xor_sync(0xffffffffu, sum, o);
    if (lid == 0) ssum[wid] = sum;
    __syncthreads();
    if (wid == 0) {
        float s = (lid < 8) ? ssum[lid] : 0.f;
        #pragma unroll
        for (int o = 4; o > 0; o >>= 1) s += __shfl_xor_sync(0xffffffffu, s, o);
        if (lid == 0) ssum[0] = s;
    }
    __syncthreads();
    const float inv = 1.f / ssum[0];

    float* prow = probs + (size_t)row * SDIM;
    float4 o0, o1;
    o0.x = v[0] * inv; o0.y = v[1] * inv; o0.z = v[2] * inv; o0.w = v[3] * inv;
    o1.x = v[4] * inv; o1.y = v[5] * inv; o1.z = v[6] * inv; o1.w = v[7] * inv;
    *(float4*)(prow + t * 4) = o0;
    *(float4*)(prow + 1024 + t * 4) = o1;
}

// ---------------------------------------------------------------------------
// FP32 SGEMM, 128x128x8 block tile, 8x8 per thread, 256 threads.
// BT = true : C[m,n] = sum_k A[m,k] * B[n,k]   (B is [N,K] row-major, "NT")
// BT = false: C[m,n] = sum_k A[m,k] * B[k,n]   (B is [K,N] row-major, "NN")
// Optional per-column bias. Batched via blockIdx.z with element strides.
// All dims assumed multiples of the tile sizes (true here).
// ---------------------------------------------------------------------------
template <bool BT>
__global__ __launch_bounds__(256) void sgemm_kernel(
    const float* __restrict__ A, const float* __restrict__ Bm,
    const float* __restrict__ bias, float* __restrict__ C,
    int M, int N, int K,
    long long sA, long long sB, long long sC)
{
    const int BM = 128, BN = 128, BK = 8;
    __shared__ float As[BK][BM];
    __shared__ float Bs[BK][BN];

    const int tid = threadIdx.x;
    const long long zb = blockIdx.z;
    A  += zb * sA;
    Bm += zb * sB;
    C  += zb * sC;
    const int bx = blockIdx.x, by = blockIdx.y;

    const int tx = tid & 15;          // 16 thread cols
    const int ty = tid >> 4;          // 16 thread rows

    // A tile load: 128 rows x 8 k, one float4 per thread
    const int arow = tid >> 1;
    const int ac4  = (tid & 1) * 4;
    const float* Ag = A + ((size_t)(by * BM + arow)) * K + ac4;

    // B tile load
    const float* Bg;
    int bkrow = 0, bnc = 0;
    if (BT) {
        Bg = Bm + ((size_t)(bx * BN + arow)) * K + ac4;   // rows along N
    } else {
        bkrow = tid >> 5;             // k index 0..7
        bnc   = (tid & 31) * 4;       // n offset
        Bg = Bm + (size_t)bkrow * N + bx * BN + bnc;
    }

    float acc[8][8];
    #pragma unroll
    for (int i = 0; i < 8; i++)
        #pragma unroll
        for (int j = 0; j < 8; j++) acc[i][j] = 0.f;

    for (int k0 = 0; k0 < K; k0 += BK) {
        float4 a = *(const float4*)Ag;
        Ag += BK;
        float4 b = *(const float4*)Bg;
        if (BT) Bg += BK; else Bg += (size_t)BK * N;

        As[ac4 + 0][arow] = a.x;
        As[ac4 + 1][arow] = a.y;
        As[ac4 + 2][arow] = a.z;
        As[ac4 + 3][arow] = a.w;
        if (BT) {
            Bs[ac4 + 0][arow] = b.x;
            Bs[ac4 + 1][arow] = b.y;
            Bs[ac4 + 2][arow] = b.z;
            Bs[ac4 + 3][arow] = b.w;
        } else {
            *(float4*)&Bs[bkrow][bnc] = b;
        }
        __syncthreads();

        #pragma unroll
        for (int kk = 0; kk < BK; kk++) {
            float ar[8], br[8];
            #pragma unroll
            for (int i = 0; i < 8; i++) ar[i] = As[kk][ty * 8 + i];
            #pragma unroll
            for (int j = 0; j < 8; j++) br[j] = Bs[kk][tx * 8 + j];
            #pragma unroll
            for (int i = 0; i < 8; i++)
                #pragma unroll
                for (int j = 0; j < 8; j++)
                    acc[i][j] = fmaf(ar[i], br[j], acc[i][j]);
        }
        __syncthreads();
    }

    // Epilogue: optional bias, vectorized stores
    float bv[8];
    #pragma unroll
    for (int j = 0; j < 8; j++)
        bv[j] = bias ? bias[bx * BN + tx * 8 + j] : 0.f;

    #pragma unroll
    for (int i = 0; i < 8; i++) {
        const int r = by * BM + ty * 8 + i;
        float* crow = C + (size_t)r * N + bx * BN + tx * 8;
        float4 o0, o1;
        o0.x = acc[i][0] + bv[0]; o0.y = acc[i][1] + bv[1];
        o0.z = acc[i][2] + bv[2]; o0.w = acc[i][3] + bv[3];
        o1.x = acc[i][4] + bv[4]; o1.y = acc[i][5] + bv[5];
        o1.z = acc[i][6] + bv[6]; o1.w = acc[i][7] + bv[7];
        *(float4*)(crow + 0) = o0;
        *(float4*)(crow + 4) = o1;
    }
}

// ---------------------------------------------------------------------------
extern "C" void kernel_launch(void* const* d_in, const int* in_sizes, int n_in,
                              void* d_out, int out_size)
{
    const float* hidden = (const float*)d_in[0];   // [B, S, H]
    const float* mask   = (const float*)d_in[1];   // [B, 1, S, S]
    const float* R      = (const float*)d_in[2];   // [S, S]
    const float* G_w    = (const float*)d_in[3];   // [H, H]
    const float* G_b    = (const float*)d_in[4];   // [H]
    const float* F_w    = (const float*)d_in[5];   // [H, H]
    const float* F_b    = (const float*)d_in[6];   // [H]
    float* out = (float*)d_out;                    // [B, S, H]

    float *probs, *values, *out1;
    cudaGetSymbolAddress((void**)&probs,  g_probs);
    cudaGetSymbolAddress((void**)&values, g_values);
    cudaGetSymbolAddress((void**)&out1,   g_out1);

    // 1) probs = softmax(R + mask)
    softmax_kernel<<<BATCH * SDIM, 256>>>(R, mask, probs);

    // 2) values = hidden @ G_w^T + G_b   (flatten B*S rows; weight shared)
    sgemm_kernel<true><<<dim3(HDIM / 128, (BATCH * SDIM) / 128, 1), 256>>>(
        hidden, G_w, G_b, values,
        BATCH * SDIM, HDIM, HDIM, 0, 0, 0);

    // 3) out1 = probs @ values  (batched NN)
    sgemm_kernel<false><<<dim3(HDIM / 128, SDIM / 128, BATCH), 256>>>(
        probs, values, nullptr, out1,
        SDIM, HDIM, SDIM,
        (long long)SDIM * SDIM, (long long)SDIM * HDIM, (long long)SDIM * HDIM);

    // 4) out = out1 @ F_w^T + F_b
    sgemm_kernel<true><<<dim3(HDIM / 128, (BATCH * SDIM) / 128, 1), 256>>>(
        out1, F_w, F_b, out,
        BATCH * SDIM, HDIM, HDIM, 0, 0, 0);
}

// round 6
// speedup vs baseline: 3.5671x; 3.5671x over previous
#include <cuda_runtime.h>
#include <cuda_fp16.h>
#include <math.h>
#include <stdint.h>

#define SDIM 2048
#define HDIM 1024
#define BATCH 4
#define MROWS (BATCH*SDIM)   // 8192

// ---------------------------------------------------------------------------
// Scratch (__device__ globals; no allocations allowed)
// ---------------------------------------------------------------------------
__device__ __half g_Xh [MROWS*HDIM];
__device__ __half g_Xl [MROWS*HDIM];
__device__ __half g_Fh [HDIM*HDIM];
__device__ __half g_Fl [HDIM*HDIM];
__device__ __half g_Gth[HDIM*HDIM];
__device__ __half g_Gtl[HDIM*HDIM];
__device__ __half g_Wh [HDIM*HDIM];
__device__ __half g_Wl [HDIM*HDIM];
__device__ __half g_Ph [(size_t)BATCH*SDIM*SDIM];
__device__ __half g_Pl [(size_t)BATCH*SDIM*SDIM];
__device__ __half g_Th [MROWS*HDIM];
__device__ __half g_Tl [MROWS*HDIM];
__device__ __half g_Tth[MROWS*HDIM];
__device__ __half g_Ttl[MROWS*HDIM];
__device__ float  g_bias[HDIM];

// ---------------------------------------------------------------------------
// Helpers
// ---------------------------------------------------------------------------
__device__ __forceinline__ uint32_t smem_u32(const void* p) {
    uint32_t a;
    asm("{ .reg .u64 t; cvta.to.shared.u64 t, %1; cvt.u32.u64 %0, t; }"
        : "=r"(a) : "l"(p));
    return a;
}
__device__ __forceinline__ void cp_async16(uint32_t dst, const void* src) {
    asm volatile("cp.async.cg.shared.global [%0], [%1], 16;\n"
                 :: "r"(dst), "l"(src) : "memory");
}
__device__ __forceinline__ void ldm_x4(uint32_t* r, uint32_t addr) {
    asm volatile("ldmatrix.sync.aligned.m8n8.x4.shared.b16 {%0,%1,%2,%3}, [%4];"
                 : "=r"(r[0]), "=r"(r[1]), "=r"(r[2]), "=r"(r[3]) : "r"(addr));
}
__device__ __forceinline__ void mma16816(float* d, const uint32_t* a,
                                         uint32_t b0, uint32_t b1) {
    asm volatile(
        "mma.sync.aligned.m16n8k16.row.col.f32.f16.f16.f32 "
        "{%0,%1,%2,%3}, {%4,%5,%6,%7}, {%8,%9}, {%0,%1,%2,%3};"
        : "+f"(d[0]), "+f"(d[1]), "+f"(d[2]), "+f"(d[3])
        : "r"(a[0]), "r"(a[1]), "r"(a[2]), "r"(a[3]), "r"(b0), "r"(b1));
}
__device__ __forceinline__ uint32_t packh2(float a, float b) {
    __half2 t = __halves2half2(__float2half_rn(a), __float2half_rn(b));
    return *reinterpret_cast<uint32_t*>(&t);
}

// ---------------------------------------------------------------------------
// fp32 -> (fp16 hi, fp16 lo) split, vectorized x4
// ---------------------------------------------------------------------------
__global__ __launch_bounds__(256) void split_kernel(
    const float* __restrict__ x, __half* __restrict__ hi,
    __half* __restrict__ lo, int n4)
{
    int i = blockIdx.x * blockDim.x + threadIdx.x;
    if (i >= n4) return;
    float4 v = ((const float4*)x)[i];
    float hx = __half2float(__float2half_rn(v.x));
    float hy = __half2float(__float2half_rn(v.y));
    float hz = __half2float(__float2half_rn(v.z));
    float hw = __half2float(__float2half_rn(v.w));
    uint2 ho, lw;
    ho.x = packh2(hx, hy);            ho.y = packh2(hz, hw);
    lw.x = packh2(v.x - hx, v.y - hy); lw.y = packh2(v.z - hz, v.w - hw);
    ((uint2*)hi)[i] = ho;
    ((uint2*)lo)[i] = lw;
}

// ---------------------------------------------------------------------------
// Transpose + split: G[o][h] fp32 -> Gt[h][o] fp16 hi/lo   (1024x1024)
// ---------------------------------------------------------------------------
__global__ __launch_bounds__(256) void tsplit_kernel(
    const float* __restrict__ G, __half* __restrict__ th, __half* __restrict__ tl)
{
    __shared__ float t[32][33];
    const int tx = threadIdx.x, ty = threadIdx.y;   // (32,8)
    const int bx = blockIdx.x, by = blockIdx.y;
    #pragma unroll
    for (int i = 0; i < 4; i++) {
        int r = i*8 + ty;
        t[r][tx] = G[(size_t)(by*32 + r) * HDIM + bx*32 + tx];
    }
    __syncthreads();
    #pragma unroll
    for (int i = 0; i < 4; i++) {
        int a = i*8 + ty;
        float v = t[tx][a];
        float h = __half2float(__float2half_rn(v));
        size_t o = (size_t)(bx*32 + a) * HDIM + by*32 + tx;
        th[o] = __float2half_rn(v);
        tl[o] = __float2half_rn(v - h);
    }
}

// ---------------------------------------------------------------------------
// Transpose fp16: in [MROWS, HDIM] -> out[b][HDIM][SDIM]
// ---------------------------------------------------------------------------
__global__ __launch_bounds__(256) void transpose_kernel(
    const __half* __restrict__ in, __half* __restrict__ out)
{
    __shared__ __half t[32][33];
    const int tx = threadIdx.x, ty = threadIdx.y;
    const int bx = blockIdx.x, by = blockIdx.y;   // (HDIM/32, MROWS/32)
    #pragma unroll
    for (int i = 0; i < 4; i++) {
        int r = i*8 + ty;
        t[r][tx] = in[(size_t)(by*32 + r) * HDIM + bx*32 + tx];
    }
    __syncthreads();
    const int b  = (by*32) / SDIM;
    const int s0 = (by*32) % SDIM;
    #pragma unroll
    for (int i = 0; i < 4; i++) {
        int a = i*8 + ty;
        out[(size_t)b * HDIM * SDIM + (size_t)(bx*32 + a) * SDIM + s0 + tx] = t[tx][a];
    }
}

// ---------------------------------------------------------------------------
// bias_total[o] = sum_h F_w[o][h]*G_b[h] + F_b[o]
// ---------------------------------------------------------------------------
__global__ __launch_bounds__(256) void bias_kernel(
    const float* __restrict__ Fw, const float* __restrict__ Gb,
    const float* __restrict__ Fb, float* __restrict__ bias)
{
    const int o = blockIdx.x;
    const int t = threadIdx.x;
    float s = 0.f;
    for (int h = t; h < HDIM; h += 256) s += Fw[(size_t)o*HDIM + h] * Gb[h];
    #pragma unroll
    for (int off = 16; off > 0; off >>= 1) s += __shfl_xor_sync(0xffffffffu, s, off);
    __shared__ float ws[8];
    if ((t & 31) == 0) ws[t >> 5] = s;
    __syncthreads();
    if (t == 0) {
        float tot = 0.f;
        #pragma unroll
        for (int w = 0; w < 8; w++) tot += ws[w];
        bias[o] = tot + Fb[o];
    }
}

// ---------------------------------------------------------------------------
// Softmax over rows of (R + mask[b,0]) -> probs fp16 hi/lo
// ---------------------------------------------------------------------------
__global__ __launch_bounds__(256) void softmax_kernel(
    const float* __restrict__ R, const float* __restrict__ mask,
    __half* __restrict__ phi, __half* __restrict__ plo)
{
    const int row = blockIdx.x;
    const int b = row / SDIM;
    const int q = row % SDIM;
    const int t = threadIdx.x;

    const float* rrow = R + (size_t)q * SDIM;
    const float* mrow = mask + ((size_t)b * SDIM + q) * SDIM;

    float v[8];
    float4 r0 = *(const float4*)(rrow + t * 4);
    float4 m0 = *(const float4*)(mrow + t * 4);
    float4 r1 = *(const float4*)(rrow + 1024 + t * 4);
    float4 m1 = *(const float4*)(mrow + 1024 + t * 4);
    v[0]=r0.x+m0.x; v[1]=r0.y+m0.y; v[2]=r0.z+m0.z; v[3]=r0.w+m0.w;
    v[4]=r1.x+m1.x; v[5]=r1.y+m1.y; v[6]=r1.z+m1.z; v[7]=r1.w+m1.w;

    float mx = v[0];
    #pragma unroll
    for (int i = 1; i < 8; i++) mx = fmaxf(mx, v[i]);
    #pragma unroll
    for (int o = 16; o > 0; o >>= 1) mx = fmaxf(mx, __shfl_xor_sync(0xffffffffu, mx, o));

    __shared__ float smx[8], ssum[8];
    const int wid = t >> 5, lid = t & 31;
    if (lid == 0) smx[wid] = mx;
    __syncthreads();
    if (wid == 0) {
        float m = (lid < 8) ? smx[lid] : -INFINITY;
        #pragma unroll
        for (int o = 4; o > 0; o >>= 1) m = fmaxf(m, __shfl_xor_sync(0xffffffffu, m, o));
        if (lid == 0) smx[0] = m;
    }
    __syncthreads();
    mx = smx[0];

    float sum = 0.f;
    #pragma unroll
    for (int i = 0; i < 8; i++) { v[i] = __expf(v[i] - mx); sum += v[i]; }
    #pragma unroll
    for (int o = 16; o > 0; o >>= 1) sum += __shfl_xor_sync(0xffffffffu, sum, o);
    if (lid == 0) ssum[wid] = sum;
    __syncthreads();
    if (wid == 0) {
        float s = (lid < 8) ? ssum[lid] : 0.f;
        #pragma unroll
        for (int o = 4; o > 0; o >>= 1) s += __shfl_xor_sync(0xffffffffu, s, o);
        if (lid == 0) ssum[0] = s;
    }
    __syncthreads();
    const float inv = 1.f / ssum[0];

    __half* ph = phi + (size_t)row * SDIM;
    __half* pl = plo + (size_t)row * SDIM;
    #pragma unroll
    for (int g = 0; g < 2; g++) {
        float f0 = v[g*4+0]*inv, f1 = v[g*4+1]*inv, f2 = v[g*4+2]*inv, f3 = v[g*4+3]*inv;
        float h0 = __half2float(__float2half_rn(f0));
        float h1 = __half2float(__float2half_rn(f1));
        float h2 = __half2float(__float2half_rn(f2));
        float h3 = __half2float(__float2half_rn(f3));
        uint2 hw2, lw2;
        hw2.x = packh2(f0, f1);       hw2.y = packh2(f2, f3);
        lw2.x = packh2(f0-h0, f1-h1); lw2.y = packh2(f2-h2, f3-h3);
        *(uint2*)(ph + g*1024 + t*4) = hw2;
        *(uint2*)(pl + g*1024 + t*4) = lw2;
    }
}

// ---------------------------------------------------------------------------
// Split-fp16 HMMA GEMM.  C[M,N] = A[M,K] * B[N,K]^T  (both K-contiguous),
// computed as Ah*Bh + Al*Bh + Ah*Bl with fp32 register accumulation.
// Tile 128x128x64, 256 threads (8 warps, warp tile 32x64, m16n8k16 HMMA).
// SW128-swizzled smem, double-buffered cp.async.
// OUT_MODE 0: write fp16 hi/lo split. 1: write fp32 + bias[col].
// ---------------------------------------------------------------------------
#define STAGE 32768u     // 16KB A + 16KB B per stage
#define GEMM_SMEM (2*STAGE)

template <int OUT_MODE>
__global__ __launch_bounds__(256)
void hgemm3(const __half* __restrict__ Ah, const __half* __restrict__ Al,
            const __half* __restrict__ Bh, const __half* __restrict__ Bl,
            const float* __restrict__ bias,
            void* __restrict__ outA, void* __restrict__ outB,
            int K, int N, long long sA, long long sB, long long sC)
{
    extern __shared__ char smem[];
    const uint32_t sb = smem_u32(smem);
    const int tid = threadIdx.x;
    const int wid = tid >> 5, lane = tid & 31;
    const long long zb = blockIdx.z;
    Ah += zb * sA; Al += zb * sA;
    Bh += zb * sB; Bl += zb * sB;
    const int row0 = blockIdx.y * 128;
    const int col0 = blockIdx.x * 128;
    const int wm0 = (wid >> 1) * 32;     // warp m offset (4 rows of warps)
    const int wn0 = (wid & 1) * 64;      // warp n offset (2 cols of warps)

    const int KC = K >> 6;               // 64-wide chunks per pass
    const int NC = 3 * KC;

    float acc[2][8][4];
    #pragma unroll
    for (int mi = 0; mi < 2; mi++)
        #pragma unroll
        for (int ni = 0; ni < 8; ni++)
            #pragma unroll
            for (int j = 0; j < 4; j++) acc[mi][ni][j] = 0.f;

    // cp.async layout: 1024 16B-chunks per operand tile, 4 per thread.
    auto load_chunk = [&](int c, int st) {
        const int pass = c / KC;
        const int k0 = (c - pass * KC) << 6;
        const __half* As = (pass == 1) ? Al : Ah;
        const __half* Bs = (pass == 2) ? Bl : Bh;
        const uint32_t ab = sb + st * STAGE;
        const uint32_t bb = ab + 16384u;
        #pragma unroll
        for (int i = 0; i < 4; i++) {
            const int idx = tid + 256 * i;        // 0..1023
            const int r = idx >> 3;               // tile row 0..127
            const int cc = idx & 7;               // 16B chunk 0..7
            const uint32_t sw = (uint32_t)r * 128u + ((uint32_t)(cc ^ (r & 7)) << 4);
            cp_async16(ab + sw, As + (size_t)(row0 + r) * K + k0 + cc * 8);
            cp_async16(bb + sw, Bs + (size_t)(col0 + r) * K + k0 + cc * 8);
        }
    };

    load_chunk(0, 0);
    asm volatile("cp.async.commit_group;" ::: "memory");

    for (int c = 0; c < NC; c++) {
        const int cur = c & 1;
        if (c + 1 < NC) {
            load_chunk(c + 1, cur ^ 1);
            asm volatile("cp.async.commit_group;" ::: "memory");
            asm volatile("cp.async.wait_group 1;" ::: "memory");
        } else {
            asm volatile("cp.async.wait_group 0;" ::: "memory");
        }
        __syncthreads();

        const uint32_t Abase = sb + cur * STAGE;
        const uint32_t Bbase = Abase + 16384u;

        #pragma unroll
        for (int kk = 0; kk < 4; kk++) {
            uint32_t af[2][4];
            #pragma unroll
            for (int mi = 0; mi < 2; mi++) {
                const int r = wm0 + mi * 16 + (lane & 15);
                const int cc = kk * 2 + (lane >> 4);
                ldm_x4(af[mi], Abase + (uint32_t)r * 128u +
                               ((uint32_t)(cc ^ (r & 7)) << 4));
            }
            uint32_t bf[4][4];
            #pragma unroll
            for (int gi = 0; gi < 4; gi++) {
                const int nr = wn0 + gi * 16 + (lane & 7) + ((lane >> 4) << 3);
                const int cc = kk * 2 + ((lane >> 3) & 1);
                ldm_x4(bf[gi], Bbase + (uint32_t)nr * 128u +
                               ((uint32_t)(cc ^ (nr & 7)) << 4));
            }
            #pragma unroll
            for (int mi = 0; mi < 2; mi++)
                #pragma unroll
                for (int ni = 0; ni < 8; ni++)
                    mma16816(acc[mi][ni], af[mi],
                             bf[ni >> 1][(ni & 1) * 2], bf[ni >> 1][(ni & 1) * 2 + 1]);
        }
        __syncthreads();
    }

    // Epilogue
    const int g = lane >> 2, q = lane & 3;
    #pragma unroll
    for (int mi = 0; mi < 2; mi++) {
        #pragma unroll
        for (int ni = 0; ni < 8; ni++) {
            const int m0 = row0 + wm0 + mi * 16 + g;
            const int cn = col0 + wn0 + ni * 8 + q * 2;
            float v0 = acc[mi][ni][0], v1 = acc[mi][ni][1];
            float v2 = acc[mi][ni][2], v3 = acc[mi][ni][3];
            if (OUT_MODE == 0) {
                __half* Oh = (__half*)outA + zb * sC;
                __half* Ol = (__half*)outB + zb * sC;
                float h0 = __half2float(__float2half_rn(v0));
                float h1 = __half2float(__float2half_rn(v1));
                float h2 = __half2float(__float2half_rn(v2));
                float h3 = __half2float(__float2half_rn(v3));
                *(uint32_t*)(Oh + (size_t)m0 * N + cn)       = packh2(v0, v1);
                *(uint32_t*)(Ol + (size_t)m0 * N + cn)       = packh2(v0 - h0, v1 - h1);
                *(uint32_t*)(Oh + (size_t)(m0 + 8) * N + cn) = packh2(v2, v3);
                *(uint32_t*)(Ol + (size_t)(m0 + 8) * N + cn) = packh2(v2 - h2, v3 - h3);
            } else {
                float* O = (float*)outA + zb * sC;
                const float b0 = bias[cn], b1 = bias[cn + 1];
                float2 p0 = make_float2(v0 + b0, v1 + b1);
                float2 p1 = make_float2(v2 + b0, v3 + b1);
                *(float2*)(O + (size_t)m0 * N + cn)       = p0;
                *(float2*)(O + (size_t)(m0 + 8) * N + cn) = p1;
            }
        }
    }
}

// ---------------------------------------------------------------------------
extern "C" void kernel_launch(void* const* d_in, const int* in_sizes, int n_in,
                              void* d_out, int out_size)
{
    const float* hidden = (const float*)d_in[0];   // [B, S, H]
    const float* mask   = (const float*)d_in[1];   // [B, 1, S, S]
    const float* R      = (const float*)d_in[2];   // [S, S]
    const float* G_w    = (const float*)d_in[3];   // [H, H]
    const float* G_b    = (const float*)d_in[4];   // [H]
    const float* F_w    = (const float*)d_in[5];   // [H, H]
    const float* F_b    = (const float*)d_in[6];   // [H]
    float* out = (float*)d_out;                    // [B, S, H]

    __half *Xh,*Xl,*Fh,*Fl,*Gth,*Gtl,*Wh,*Wl,*Ph,*Pl,*Th,*Tl,*Tth,*Ttl;
    float* bias;
    cudaGetSymbolAddress((void**)&Xh,  g_Xh);
    cudaGetSymbolAddress((void**)&Xl,  g_Xl);
    cudaGetSymbolAddress((void**)&Fh,  g_Fh);
    cudaGetSymbolAddress((void**)&Fl,  g_Fl);
    cudaGetSymbolAddress((void**)&Gth, g_Gth);
    cudaGetSymbolAddress((void**)&Gtl, g_Gtl);
    cudaGetSymbolAddress((void**)&Wh,  g_Wh);
    cudaGetSymbolAddress((void**)&Wl,  g_Wl);
    cudaGetSymbolAddress((void**)&Ph,  g_Ph);
    cudaGetSymbolAddress((void**)&Pl,  g_Pl);
    cudaGetSymbolAddress((void**)&Th,  g_Th);
    cudaGetSymbolAddress((void**)&Tl,  g_Tl);
    cudaGetSymbolAddress((void**)&Tth, g_Tth);
    cudaGetSymbolAddress((void**)&Ttl, g_Ttl);
    cudaGetSymbolAddress((void**)&bias, g_bias);

    cudaFuncSetAttribute((const void*)&hgemm3<0>,
                         cudaFuncAttributeMaxDynamicSharedMemorySize, GEMM_SMEM);
    cudaFuncSetAttribute((const void*)&hgemm3<1>,
                         cudaFuncAttributeMaxDynamicSharedMemorySize, GEMM_SMEM);

    // Splits + transposed split of G
    split_kernel<<<MROWS*HDIM/4/256, 256>>>(hidden, Xh, Xl, MROWS*HDIM/4);
    split_kernel<<<HDIM*HDIM/4/256, 256>>>(F_w, Fh, Fl, HDIM*HDIM/4);
    tsplit_kernel<<<dim3(HDIM/32, HDIM/32), dim3(32, 8)>>>(G_w, Gth, Gtl);

    // Softmax -> probs hi/lo ; fused bias
    softmax_kernel<<<BATCH*SDIM, 256>>>(R, mask, Ph, Pl);
    bias_kernel<<<HDIM, 256>>>(F_w, G_b, F_b, bias);

    // W = F_w @ G_w  (A=F [o,k], B=Gt [j,k]) -> fp16 hi/lo
    hgemm3<0><<<dim3(8, 8, 1), 256, GEMM_SMEM>>>(
        Fh, Fl, Gth, Gtl, nullptr, Wh, Wl, HDIM, HDIM, 0, 0, 0);

    // T = X @ W^T -> fp16 hi/lo
    hgemm3<0><<<dim3(8, 64, 1), 256, GEMM_SMEM>>>(
        Xh, Xl, Wh, Wl, nullptr, Th, Tl, HDIM, HDIM, 0, 0, 0);

    // Transpose T -> per-batch [H, S]
    transpose_kernel<<<dim3(HDIM/32, MROWS/32), dim3(32, 8)>>>(Th, Tth);
    transpose_kernel<<<dim3(HDIM/32, MROWS/32), dim3(32, 8)>>>(Tl, Ttl);

    // out = P @ T + bias_total  (batched, fp32 out)
    hgemm3<1><<<dim3(8, 16, 4), 256, GEMM_SMEM>>>(
        Ph, Pl, Tth, Ttl, bias, out, nullptr,
        SDIM, HDIM,
        (long long)SDIM * SDIM, (long long)HDIM * SDIM, (long long)SDIM * HDIM);
}

// round 7
// speedup vs baseline: 5.2291x; 1.4659x over previous
#include <cuda_runtime.h>
#include <cuda_fp16.h>
#include <math.h>
#include <stdint.h>

#define SDIM 2048
#define HDIM 1024
#define BATCH 4
#define MROWS (BATCH*SDIM)   // 8192

// ---------------------------------------------------------------------------
// Scratch (__device__ globals; no allocations allowed)
// ---------------------------------------------------------------------------
__device__ __half g_Xh [MROWS*HDIM];
__device__ __half g_Xl [MROWS*HDIM];
__device__ __half g_Fh [HDIM*HDIM];
__device__ __half g_Fl [HDIM*HDIM];
__device__ __half g_Gth[HDIM*HDIM];
__device__ __half g_Wh [HDIM*HDIM];
__device__ __half g_Ph [(size_t)BATCH*SDIM*SDIM];
__device__ __half g_Pl [(size_t)BATCH*SDIM*SDIM];
__device__ __half g_Th [MROWS*HDIM];
__device__ __half g_Tth[MROWS*HDIM];
__device__ float  g_bias[HDIM];

// ---------------------------------------------------------------------------
// Helpers
// ---------------------------------------------------------------------------
__device__ __forceinline__ uint32_t smem_u32(const void* p) {
    uint32_t a;
    asm("{ .reg .u64 t; cvta.to.shared.u64 t, %1; cvt.u32.u64 %0, t; }"
        : "=r"(a) : "l"(p));
    return a;
}
__device__ __forceinline__ void cp_async16(uint32_t dst, const void* src) {
    asm volatile("cp.async.cg.shared.global [%0], [%1], 16;\n"
                 :: "r"(dst), "l"(src) : "memory");
}
__device__ __forceinline__ void ldm_x4(uint32_t* r, uint32_t addr) {
    asm volatile("ldmatrix.sync.aligned.m8n8.x4.shared.b16 {%0,%1,%2,%3}, [%4];"
                 : "=r"(r[0]), "=r"(r[1]), "=r"(r[2]), "=r"(r[3]) : "r"(addr));
}
__device__ __forceinline__ void mma16816(float* d, const uint32_t* a,
                                         uint32_t b0, uint32_t b1) {
    asm volatile(
        "mma.sync.aligned.m16n8k16.row.col.f32.f16.f16.f32 "
        "{%0,%1,%2,%3}, {%4,%5,%6,%7}, {%8,%9}, {%0,%1,%2,%3};"
        : "+f"(d[0]), "+f"(d[1]), "+f"(d[2]), "+f"(d[3])
        : "r"(a[0]), "r"(a[1]), "r"(a[2]), "r"(a[3]), "r"(b0), "r"(b1));
}
__device__ __forceinline__ uint32_t packh2(float a, float b) {
    __half2 t = __halves2half2(__float2half_rn(a), __float2half_rn(b));
    return *reinterpret_cast<uint32_t*>(&t);
}

// ---------------------------------------------------------------------------
// fp32 -> (fp16 hi, fp16 lo) split, vectorized x4
// ---------------------------------------------------------------------------
__global__ __launch_bounds__(256) void split_kernel(
    const float* __restrict__ x, __half* __restrict__ hi,
    __half* __restrict__ lo, int n4)
{
    int i = blockIdx.x * blockDim.x + threadIdx.x;
    if (i >= n4) return;
    float4 v = ((const float4*)x)[i];
    float hx = __half2float(__float2half_rn(v.x));
    float hy = __half2float(__float2half_rn(v.y));
    float hz = __half2float(__float2half_rn(v.z));
    float hw = __half2float(__float2half_rn(v.w));
    uint2 ho, lw;
    ho.x = packh2(hx, hy);             ho.y = packh2(hz, hw);
    lw.x = packh2(v.x - hx, v.y - hy); lw.y = packh2(v.z - hz, v.w - hw);
    ((uint2*)hi)[i] = ho;
    ((uint2*)lo)[i] = lw;
}

// ---------------------------------------------------------------------------
// Transpose: G[o][h] fp32 -> Gt[h][o] fp16 (hi only)   (1024x1024)
// ---------------------------------------------------------------------------
__global__ __launch_bounds__(256) void tsplit_kernel(
    const float* __restrict__ G, __half* __restrict__ th)
{
    __shared__ float t[32][33];
    const int tx = threadIdx.x, ty = threadIdx.y;   // (32,8)
    const int bx = blockIdx.x, by = blockIdx.y;
    #pragma unroll
    for (int i = 0; i < 4; i++) {
        int r = i*8 + ty;
        t[r][tx] = G[(size_t)(by*32 + r) * HDIM + bx*32 + tx];
    }
    __syncthreads();
    #pragma unroll
    for (int i = 0; i < 4; i++) {
        int a = i*8 + ty;
        th[(size_t)(bx*32 + a) * HDIM + by*32 + tx] = __float2half_rn(t[tx][a]);
    }
}

// ---------------------------------------------------------------------------
// Transpose fp16: in [MROWS, HDIM] -> out[b][HDIM][SDIM]
// ---------------------------------------------------------------------------
__global__ __launch_bounds__(256) void transpose_kernel(
    const __half* __restrict__ in, __half* __restrict__ out)
{
    __shared__ __half t[32][33];
    const int tx = threadIdx.x, ty = threadIdx.y;
    const int bx = blockIdx.x, by = blockIdx.y;   // (HDIM/32, MROWS/32)
    #pragma unroll
    for (int i = 0; i < 4; i++) {
        int r = i*8 + ty;
        t[r][tx] = in[(size_t)(by*32 + r) * HDIM + bx*32 + tx];
    }
    __syncthreads();
    const int b  = (by*32) / SDIM;
    const int s0 = (by*32) % SDIM;
    #pragma unroll
    for (int i = 0; i < 4; i++) {
        int a = i*8 + ty;
        out[(size_t)b * HDIM * SDIM + (size_t)(bx*32 + a) * SDIM + s0 + tx] = t[tx][a];
    }
}

// ---------------------------------------------------------------------------
// bias_total[o] = sum_h F_w[o][h]*G_b[h] + F_b[o]
// ---------------------------------------------------------------------------
__global__ __launch_bounds__(256) void bias_kernel(
    const float* __restrict__ Fw, const float* __restrict__ Gb,
    const float* __restrict__ Fb, float* __restrict__ bias)
{
    const int o = blockIdx.x;
    const int t = threadIdx.x;
    float s = 0.f;
    for (int h = t; h < HDIM; h += 256) s += Fw[(size_t)o*HDIM + h] * Gb[h];
    #pragma unroll
    for (int off = 16; off > 0; off >>= 1) s += __shfl_xor_sync(0xffffffffu, s, off);
    __shared__ float ws[8];
    if ((t & 31) == 0) ws[t >> 5] = s;
    __syncthreads();
    if (t == 0) {
        float tot = 0.f;
        #pragma unroll
        for (int w = 0; w < 8; w++) tot += ws[w];
        bias[o] = tot + Fb[o];
    }
}

// ---------------------------------------------------------------------------
// Softmax over rows of (R + mask[b,0]) -> probs fp16 hi/lo
// ---------------------------------------------------------------------------
__global__ __launch_bounds__(256) void softmax_kernel(
    const float* __restrict__ R, const float* __restrict__ mask,
    __half* __restrict__ phi, __half* __restrict__ plo)
{
    const int row = blockIdx.x;
    const int b = row / SDIM;
    const int q = row % SDIM;
    const int t = threadIdx.x;

    const float* rrow = R + (size_t)q * SDIM;
    const float* mrow = mask + ((size_t)b * SDIM + q) * SDIM;

    float v[8];
    float4 r0 = *(const float4*)(rrow + t * 4);
    float4 m0 = *(const float4*)(mrow + t * 4);
    float4 r1 = *(const float4*)(rrow + 1024 + t * 4);
    float4 m1 = *(const float4*)(mrow + 1024 + t * 4);
    v[0]=r0.x+m0.x; v[1]=r0.y+m0.y; v[2]=r0.z+m0.z; v[3]=r0.w+m0.w;
    v[4]=r1.x+m1.x; v[5]=r1.y+m1.y; v[6]=r1.z+m1.z; v[7]=r1.w+m1.w;

    float mx = v[0];
    #pragma unroll
    for (int i = 1; i < 8; i++) mx = fmaxf(mx, v[i]);
    #pragma unroll
    for (int o = 16; o > 0; o >>= 1) mx = fmaxf(mx, __shfl_xor_sync(0xffffffffu, mx, o));

    __shared__ float smx[8], ssum[8];
    const int wid = t >> 5, lid = t & 31;
    if (lid == 0) smx[wid] = mx;
    __syncthreads();
    if (wid == 0) {
        float m = (lid < 8) ? smx[lid] : -INFINITY;
        #pragma unroll
        for (int o = 4; o > 0; o >>= 1) m = fmaxf(m, __shfl_xor_sync(0xffffffffu, m, o));
        if (lid == 0) smx[0] = m;
    }
    __syncthreads();
    mx = smx[0];

    float sum = 0.f;
    #pragma unroll
    for (int i = 0; i < 8; i++) { v[i] = __expf(v[i] - mx); sum += v[i]; }
    #pragma unroll
    for (int o = 16; o > 0; o >>= 1) sum += __shfl_xor_sync(0xffffffffu, sum, o);
    if (lid == 0) ssum[wid] = sum;
    __syncthreads();
    if (wid == 0) {
        float s = (lid < 8) ? ssum[lid] : 0.f;
        #pragma unroll
        for (int o = 4; o > 0; o >>= 1) s += __shfl_xor_sync(0xffffffffu, s, o);
        if (lid == 0) ssum[0] = s;
    }
    __syncthreads();
    const float inv = 1.f / ssum[0];

    __half* ph = phi + (size_t)row * SDIM;
    __half* pl = plo + (size_t)row * SDIM;
    #pragma unroll
    for (int g = 0; g < 2; g++) {
        float f0 = v[g*4+0]*inv, f1 = v[g*4+1]*inv, f2 = v[g*4+2]*inv, f3 = v[g*4+3]*inv;
        float h0 = __half2float(__float2half_rn(f0));
        float h1 = __half2float(__float2half_rn(f1));
        float h2 = __half2float(__float2half_rn(f2));
        float h3 = __half2float(__float2half_rn(f3));
        uint2 hw2, lw2;
        hw2.x = packh2(f0, f1);       hw2.y = packh2(f2, f3);
        lw2.x = packh2(f0-h0, f1-h1); lw2.y = packh2(f2-h2, f3-h3);
        *(uint2*)(ph + g*1024 + t*4) = hw2;
        *(uint2*)(pl + g*1024 + t*4) = lw2;
    }
}

// ---------------------------------------------------------------------------
// Fused 2-pass split-fp16 HMMA GEMM.
//   C[M,N] = (Ah + Al)[M,K] * Bh[N,K]^T   (all K-contiguous)
// Per K-chunk (64): load {Ah,Al,B} tiles into one 48KB stage; B fragments are
// shared by both MMA passes. 3-stage cp.async ring, prefetch depth 2, ONE
// __syncthreads per chunk. Tile 128x128x64, 256 thr, warp tile 32x64, HMMA
// m16n8k16, fp32 accum carried across both passes.
// OUT_MODE 0: write fp16 (hi only). 1: write fp32 + bias[col].
// ---------------------------------------------------------------------------
#define STAGE 49152u                  // 16KB Ah + 16KB Al + 16KB B
#define GEMM_SMEM (3*STAGE)           // 144 KB

template <int OUT_MODE>
__global__ __launch_bounds__(256)
void hgemm_fused(const __half* __restrict__ Ah, const __half* __restrict__ Al,
                 const __half* __restrict__ Bh,
                 const float* __restrict__ bias, void* __restrict__ outp,
                 int K, int N, long long sA, long long sB, long long sC)
{
    extern __shared__ char smem[];
    const uint32_t sb = smem_u32(smem);
    const int tid = threadIdx.x;
    const int wid = tid >> 5, lane = tid & 31;
    const long long zb = blockIdx.z;
    Ah += zb * sA; Al += zb * sA; Bh += zb * sB;
    const int row0 = blockIdx.y * 128;
    const int col0 = blockIdx.x * 128;
    const int wm0 = (wid >> 1) * 32;
    const int wn0 = (wid & 1) * 64;

    const int NC = K >> 6;

    float acc[2][8][4];
    #pragma unroll
    for (int mi = 0; mi < 2; mi++)
        #pragma unroll
        for (int ni = 0; ni < 8; ni++)
            #pragma unroll
            for (int j = 0; j < 4; j++) acc[mi][ni][j] = 0.f;

    auto load_chunk = [&](int c, int st) {
        const int k0 = c << 6;
        const uint32_t ahb = sb + st * STAGE;
        const uint32_t alb = ahb + 16384u;
        const uint32_t bb  = ahb + 32768u;
        #pragma unroll
        for (int i = 0; i < 4; i++) {
            const int idx = tid + 256 * i;        // 0..1023
            const int r = idx >> 3;               // tile row 0..127
            const int cc = idx & 7;               // 16B chunk 0..7
            const uint32_t sw = (uint32_t)r * 128u + ((uint32_t)(cc ^ (r & 7)) << 4);
            const size_t ga = (size_t)(row0 + r) * K + k0 + cc * 8;
            cp_async16(ahb + sw, Ah + ga);
            cp_async16(alb + sw, Al + ga);
            cp_async16(bb  + sw, Bh + (size_t)(col0 + r) * K + k0 + cc * 8);
        }
        asm volatile("cp.async.commit_group;" ::: "memory");
    };

    load_chunk(0, 0);
    if (NC > 1) load_chunk(1, 1);

    for (int c = 0; c < NC; c++) {
        if (c + 1 < NC) { asm volatile("cp.async.wait_group 1;" ::: "memory"); }
        else            { asm volatile("cp.async.wait_group 0;" ::: "memory"); }
        __syncthreads();
        if (c + 2 < NC) load_chunk(c + 2, (c + 2) % 3);

        const uint32_t ahb = sb + (c % 3) * STAGE;
        const uint32_t alb = ahb + 16384u;
        const uint32_t bb  = ahb + 32768u;

        #pragma unroll
        for (int kk = 0; kk < 4; kk++) {
            uint32_t af[2][4], lf[2][4];
            #pragma unroll
            for (int mi = 0; mi < 2; mi++) {
                const int r = wm0 + mi * 16 + (lane & 15);
                const int cc = kk * 2 + (lane >> 4);
                const uint32_t off = (uint32_t)r * 128u + ((uint32_t)(cc ^ (r & 7)) << 4);
                ldm_x4(af[mi], ahb + off);
                ldm_x4(lf[mi], alb + off);
            }
            uint32_t bf[4][4];
            #pragma unroll
            for (int gi = 0; gi < 4; gi++) {
                const int nr = wn0 + gi * 16 + (lane & 7) + ((lane >> 4) << 3);
                const int cc = kk * 2 + ((lane >> 3) & 1);
                ldm_x4(bf[gi], bb + (uint32_t)nr * 128u +
                               ((uint32_t)(cc ^ (nr & 7)) << 4));
            }
            #pragma unroll
            for (int mi = 0; mi < 2; mi++)
                #pragma unroll
                for (int ni = 0; ni < 8; ni++) {
                    const uint32_t b0 = bf[ni >> 1][(ni & 1) * 2];
                    const uint32_t b1 = bf[ni >> 1][(ni & 1) * 2 + 1];
                    mma16816(acc[mi][ni], af[mi], b0, b1);
                    mma16816(acc[mi][ni], lf[mi], b0, b1);
                }
        }
    }

    // Epilogue
    const int g = lane >> 2, q = lane & 3;
    #pragma unroll
    for (int mi = 0; mi < 2; mi++) {
        #pragma unroll
        for (int ni = 0; ni < 8; ni++) {
            const int m0 = row0 + wm0 + mi * 16 + g;
            const int cn = col0 + wn0 + ni * 8 + q * 2;
            float v0 = acc[mi][ni][0], v1 = acc[mi][ni][1];
            float v2 = acc[mi][ni][2], v3 = acc[mi][ni][3];
            if (OUT_MODE == 0) {
                __half* Oh = (__half*)outp + zb * sC;
                *(uint32_t*)(Oh + (size_t)m0 * N + cn)       = packh2(v0, v1);
                *(uint32_t*)(Oh + (size_t)(m0 + 8) * N + cn) = packh2(v2, v3);
            } else {
                float* O = (float*)outp + zb * sC;
                const float b0 = bias[cn], b1 = bias[cn + 1];
                *(float2*)(O + (size_t)m0 * N + cn)       = make_float2(v0 + b0, v1 + b1);
                *(float2*)(O + (size_t)(m0 + 8) * N + cn) = make_float2(v2 + b0, v3 + b1);
            }
        }
    }
}

// ---------------------------------------------------------------------------
extern "C" void kernel_launch(void* const* d_in, const int* in_sizes, int n_in,
                              void* d_out, int out_size)
{
    const float* hidden = (const float*)d_in[0];   // [B, S, H]
    const float* mask   = (const float*)d_in[1];   // [B, 1, S, S]
    const float* R      = (const float*)d_in[2];   // [S, S]
    const float* G_w    = (const float*)d_in[3];   // [H, H]
    const float* G_b    = (const float*)d_in[4];   // [H]
    const float* F_w    = (const float*)d_in[5];   // [H, H]
    const float* F_b    = (const float*)d_in[6];   // [H]
    float* out = (float*)d_out;                    // [B, S, H]

    __half *Xh,*Xl,*Fh,*Fl,*Gth,*Wh,*Ph,*Pl,*Th,*Tth;
    float* bias;
    cudaGetSymbolAddress((void**)&Xh,  g_Xh);
    cudaGetSymbolAddress((void**)&Xl,  g_Xl);
    cudaGetSymbolAddress((void**)&Fh,  g_Fh);
    cudaGetSymbolAddress((void**)&Fl,  g_Fl);
    cudaGetSymbolAddress((void**)&Gth, g_Gth);
    cudaGetSymbolAddress((void**)&Wh,  g_Wh);
    cudaGetSymbolAddress((void**)&Ph,  g_Ph);
    cudaGetSymbolAddress((void**)&Pl,  g_Pl);
    cudaGetSymbolAddress((void**)&Th,  g_Th);
    cudaGetSymbolAddress((void**)&Tth, g_Tth);
    cudaGetSymbolAddress((void**)&bias, g_bias);

    cudaFuncSetAttribute((const void*)&hgemm_fused<0>,
                         cudaFuncAttributeMaxDynamicSharedMemorySize, GEMM_SMEM);
    cudaFuncSetAttribute((const void*)&hgemm_fused<1>,
                         cudaFuncAttributeMaxDynamicSharedMemorySize, GEMM_SMEM);

    // Splits (X, F hi/lo; G transposed hi)
    split_kernel<<<MROWS*HDIM/4/256, 256>>>(hidden, Xh, Xl, MROWS*HDIM/4);
    split_kernel<<<HDIM*HDIM/4/256, 256>>>(F_w, Fh, Fl, HDIM*HDIM/4);
    tsplit_kernel<<<dim3(HDIM/32, HDIM/32), dim3(32, 8)>>>(G_w, Gth);

    // Softmax -> probs hi/lo ; fused bias
    softmax_kernel<<<BATCH*SDIM, 256>>>(R, mask, Ph, Pl);
    bias_kernel<<<HDIM, 256>>>(F_w, G_b, F_b, bias);

    // W = F @ Gh  (2-pass on F side) -> fp16 hi
    hgemm_fused<0><<<dim3(8, 8, 1), 256, GEMM_SMEM>>>(
        Fh, Fl, Gth, nullptr, Wh, HDIM, HDIM, 0, 0, 0);

    // T = X @ Wh^T  (2-pass on X side) -> fp16 hi
    hgemm_fused<0><<<dim3(8, 64, 1), 256, GEMM_SMEM>>>(
        Xh, Xl, Wh, nullptr, Th, HDIM, HDIM, 0, 0, 0);

    // Transpose T -> per-batch [H, S]
    transpose_kernel<<<dim3(HDIM/32, MROWS/32), dim3(32, 8)>>>(Th, Tth);

    // out = P @ Th + bias_total  (2-pass on P side, batched, fp32 out)
    hgemm_fused<1><<<dim3(8, 16, 4), 256, GEMM_SMEM>>>(
        Ph, Pl, Tth, bias, out,
        SDIM, HDIM,
        (long long)SDIM * SDIM, (long long)HDIM * SDIM, (long long)SDIM * HDIM);
}

// round 8
// speedup vs baseline: 8.7418x; 1.6718x over previous
#include <cuda_runtime.h>
#include <cuda_fp16.h>
#include <math.h>
#include <stdint.h>

#define SDIM 2048
#define HDIM 1024
#define BATCH 4
#define MROWS (BATCH*SDIM)   // 8192

// ---------------------------------------------------------------------------
// Scratch (__device__ globals; no allocations allowed)
// ---------------------------------------------------------------------------
__device__ __half g_Xh [MROWS*HDIM];
__device__ __half g_Fh [HDIM*HDIM];
__device__ __half g_Gth[HDIM*HDIM];
__device__ __half g_Wh [HDIM*HDIM];
__device__ __half g_Ph [(size_t)BATCH*SDIM*SDIM];
__device__ __half g_Th [MROWS*HDIM];
__device__ __half g_Tth[MROWS*HDIM];
__device__ float  g_bias[HDIM];

// ---------------------------------------------------------------------------
// Helpers
// ---------------------------------------------------------------------------
__device__ __forceinline__ uint32_t smem_u32(const void* p) {
    uint32_t a;
    asm("{ .reg .u64 t; cvta.to.shared.u64 t, %1; cvt.u32.u64 %0, t; }"
        : "=r"(a) : "l"(p));
    return a;
}
__device__ __forceinline__ void cp_async16(uint32_t dst, const void* src) {
    asm volatile("cp.async.cg.shared.global [%0], [%1], 16;\n"
                 :: "r"(dst), "l"(src) : "memory");
}
__device__ __forceinline__ void ldm_x4(uint32_t* r, uint32_t addr) {
    asm volatile("ldmatrix.sync.aligned.m8n8.x4.shared.b16 {%0,%1,%2,%3}, [%4];"
                 : "=r"(r[0]), "=r"(r[1]), "=r"(r[2]), "=r"(r[3]) : "r"(addr));
}
__device__ __forceinline__ void mma16816(float* d, const uint32_t* a,
                                         uint32_t b0, uint32_t b1) {
    asm volatile(
        "mma.sync.aligned.m16n8k16.row.col.f32.f16.f16.f32 "
        "{%0,%1,%2,%3}, {%4,%5,%6,%7}, {%8,%9}, {%0,%1,%2,%3};"
        : "+f"(d[0]), "+f"(d[1]), "+f"(d[2]), "+f"(d[3])
        : "r"(a[0]), "r"(a[1]), "r"(a[2]), "r"(a[3]), "r"(b0), "r"(b1));
}
__device__ __forceinline__ uint32_t packh2(float a, float b) {
    __half2 t = __halves2half2(__float2half_rn(a), __float2half_rn(b));
    return *reinterpret_cast<uint32_t*>(&t);
}

// ---------------------------------------------------------------------------
// fp32 -> fp16 convert, vectorized x4
// ---------------------------------------------------------------------------
__global__ __launch_bounds__(256) void conv_kernel(
    const float* __restrict__ x, __half* __restrict__ h, int n4)
{
    int i = blockIdx.x * blockDim.x + threadIdx.x;
    if (i >= n4) return;
    float4 v = ((const float4*)x)[i];
    uint2 o;
    o.x = packh2(v.x, v.y);
    o.y = packh2(v.z, v.w);
    ((uint2*)h)[i] = o;
}

// ---------------------------------------------------------------------------
// Transpose: G[o][h] fp32 -> Gt[h][o] fp16   (1024x1024)
// ---------------------------------------------------------------------------
__global__ __launch_bounds__(256) void tsplit_kernel(
    const float* __restrict__ G, __half* __restrict__ th)
{
    __shared__ float t[32][33];
    const int tx = threadIdx.x, ty = threadIdx.y;   // (32,8)
    const int bx = blockIdx.x, by = blockIdx.y;
    #pragma unroll
    for (int i = 0; i < 4; i++) {
        int r = i*8 + ty;
        t[r][tx] = G[(size_t)(by*32 + r) * HDIM + bx*32 + tx];
    }
    __syncthreads();
    #pragma unroll
    for (int i = 0; i < 4; i++) {
        int a = i*8 + ty;
        th[(size_t)(bx*32 + a) * HDIM + by*32 + tx] = __float2half_rn(t[tx][a]);
    }
}

// ---------------------------------------------------------------------------
// Transpose fp16: in [MROWS, HDIM] -> out[b][HDIM][SDIM]
// ---------------------------------------------------------------------------
__global__ __launch_bounds__(256) void transpose_kernel(
    const __half* __restrict__ in, __half* __restrict__ out)
{
    __shared__ __half t[32][33];
    const int tx = threadIdx.x, ty = threadIdx.y;
    const int bx = blockIdx.x, by = blockIdx.y;   // (HDIM/32, MROWS/32)
    #pragma unroll
    for (int i = 0; i < 4; i++) {
        int r = i*8 + ty;
        t[r][tx] = in[(size_t)(by*32 + r) * HDIM + bx*32 + tx];
    }
    __syncthreads();
    const int b  = (by*32) / SDIM;
    const int s0 = (by*32) % SDIM;
    #pragma unroll
    for (int i = 0; i < 4; i++) {
        int a = i*8 + ty;
        out[(size_t)b * HDIM * SDIM + (size_t)(bx*32 + a) * SDIM + s0 + tx] = t[tx][a];
    }
}

// ---------------------------------------------------------------------------
// bias_total[o] = sum_h F_w[o][h]*G_b[h] + F_b[o]
// ---------------------------------------------------------------------------
__global__ __launch_bounds__(256) void bias_kernel(
    const float* __restrict__ Fw, const float* __restrict__ Gb,
    const float* __restrict__ Fb, float* __restrict__ bias)
{
    const int o = blockIdx.x;
    const int t = threadIdx.x;
    float s = 0.f;
    for (int h = t; h < HDIM; h += 256) s += Fw[(size_t)o*HDIM + h] * Gb[h];
    #pragma unroll
    for (int off = 16; off > 0; off >>= 1) s += __shfl_xor_sync(0xffffffffu, s, off);
    __shared__ float ws[8];
    if ((t & 31) == 0) ws[t >> 5] = s;
    __syncthreads();
    if (t == 0) {
        float tot = 0.f;
        #pragma unroll
        for (int w = 0; w < 8; w++) tot += ws[w];
        bias[o] = tot + Fb[o];
    }
}

// ---------------------------------------------------------------------------
// Softmax over rows of (R + mask[b,0]) -> probs fp16
// ---------------------------------------------------------------------------
__global__ __launch_bounds__(256) void softmax_kernel(
    const float* __restrict__ R, const float* __restrict__ mask,
    __half* __restrict__ phi)
{
    const int row = blockIdx.x;
    const int b = row / SDIM;
    const int q = row % SDIM;
    const int t = threadIdx.x;

    const float* rrow = R + (size_t)q * SDIM;
    const float* mrow = mask + ((size_t)b * SDIM + q) * SDIM;

    float v[8];
    float4 r0 = *(const float4*)(rrow + t * 4);
    float4 m0 = *(const float4*)(mrow + t * 4);
    float4 r1 = *(const float4*)(rrow + 1024 + t * 4);
    float4 m1 = *(const float4*)(mrow + 1024 + t * 4);
    v[0]=r0.x+m0.x; v[1]=r0.y+m0.y; v[2]=r0.z+m0.z; v[3]=r0.w+m0.w;
    v[4]=r1.x+m1.x; v[5]=r1.y+m1.y; v[6]=r1.z+m1.z; v[7]=r1.w+m1.w;

    float mx = v[0];
    #pragma unroll
    for (int i = 1; i < 8; i++) mx = fmaxf(mx, v[i]);
    #pragma unroll
    for (int o = 16; o > 0; o >>= 1) mx = fmaxf(mx, __shfl_xor_sync(0xffffffffu, mx, o));

    __shared__ float smx[8], ssum[8];
    const int wid = t >> 5, lid = t & 31;
    if (lid == 0) smx[wid] = mx;
    __syncthreads();
    if (wid == 0) {
        float m = (lid < 8) ? smx[lid] : -INFINITY;
        #pragma unroll
        for (int o = 4; o > 0; o >>= 1) m = fmaxf(m, __shfl_xor_sync(0xffffffffu, m, o));
        if (lid == 0) smx[0] = m;
    }
    __syncthreads();
    mx = smx[0];

    float sum = 0.f;
    #pragma unroll
    for (int i = 0; i < 8; i++) { v[i] = __expf(v[i] - mx); sum += v[i]; }
    #pragma unroll
    for (int o = 16; o > 0; o >>= 1) sum += __shfl_xor_sync(0xffffffffu, sum, o);
    if (lid == 0) ssum[wid] = sum;
    __syncthreads();
    if (wid == 0) {
        float s = (lid < 8) ? ssum[lid] : 0.f;
        #pragma unroll
        for (int o = 4; o > 0; o >>= 1) s += __shfl_xor_sync(0xffffffffu, s, o);
        if (lid == 0) ssum[0] = s;
    }
    __syncthreads();
    const float inv = 1.f / ssum[0];

    __half* ph = phi + (size_t)row * SDIM;
    #pragma unroll
    for (int g = 0; g < 2; g++) {
        uint2 hw2;
        hw2.x = packh2(v[g*4+0]*inv, v[g*4+1]*inv);
        hw2.y = packh2(v[g*4+2]*inv, v[g*4+3]*inv);
        *(uint2*)(ph + g*1024 + t*4) = hw2;
    }
}

// ---------------------------------------------------------------------------
// Single-pass fp16 HMMA GEMM.  C[M,N] = A[M,K] * B[N,K]^T (both K-contiguous),
// fp32 register accumulation. Tile 128x128x64, 256 thr (8 warps, warp tile
// 32x64, m16n8k16). SW128-swizzled smem, 3-stage cp.async ring (32KB/stage),
// prefetch depth 2, one __syncthreads per K-chunk.
// OUT_MODE 0: write fp16. 1: write fp32 + bias[col].
// ---------------------------------------------------------------------------
#define STAGE 32768u                  // 16KB A + 16KB B
#define GEMM_SMEM (3*STAGE)           // 96 KB

template <int OUT_MODE>
__global__ __launch_bounds__(256)
void hgemm(const __half* __restrict__ Ah, const __half* __restrict__ Bh,
           const float* __restrict__ bias, void* __restrict__ outp,
           int K, int N, long long sA, long long sB, long long sC)
{
    extern __shared__ char smem[];
    const uint32_t sb = smem_u32(smem);
    const int tid = threadIdx.x;
    const int wid = tid >> 5, lane = tid & 31;
    const long long zb = blockIdx.z;
    Ah += zb * sA; Bh += zb * sB;
    const int row0 = blockIdx.y * 128;
    const int col0 = blockIdx.x * 128;
    const int wm0 = (wid >> 1) * 32;
    const int wn0 = (wid & 1) * 64;

    const int NC = K >> 6;

    float acc[2][8][4];
    #pragma unroll
    for (int mi = 0; mi < 2; mi++)
        #pragma unroll
        for (int ni = 0; ni < 8; ni++)
            #pragma unroll
            for (int j = 0; j < 4; j++) acc[mi][ni][j] = 0.f;

    auto load_chunk = [&](int c, int st) {
        const int k0 = c << 6;
        const uint32_t ab = sb + st * STAGE;
        const uint32_t bb = ab + 16384u;
        #pragma unroll
        for (int i = 0; i < 4; i++) {
            const int idx = tid + 256 * i;        // 0..1023
            const int r = idx >> 3;               // tile row 0..127
            const int cc = idx & 7;               // 16B chunk 0..7
            const uint32_t sw = (uint32_t)r * 128u + ((uint32_t)(cc ^ (r & 7)) << 4);
            cp_async16(ab + sw, Ah + (size_t)(row0 + r) * K + k0 + cc * 8);
            cp_async16(bb + sw, Bh + (size_t)(col0 + r) * K + k0 + cc * 8);
        }
        asm volatile("cp.async.commit_group;" ::: "memory");
    };

    load_chunk(0, 0);
    if (NC > 1) load_chunk(1, 1);

    for (int c = 0; c < NC; c++) {
        if (c + 1 < NC) { asm volatile("cp.async.wait_group 1;" ::: "memory"); }
        else            { asm volatile("cp.async.wait_group 0;" ::: "memory"); }
        __syncthreads();
        if (c + 2 < NC) load_chunk(c + 2, (c + 2) % 3);

        const uint32_t ab = sb + (c % 3) * STAGE;
        const uint32_t bb = ab + 16384u;

        #pragma unroll
        for (int kk = 0; kk < 4; kk++) {
            uint32_t af[2][4];
            #pragma unroll
            for (int mi = 0; mi < 2; mi++) {
                const int r = wm0 + mi * 16 + (lane & 15);
                const int cc = kk * 2 + (lane >> 4);
                ldm_x4(af[mi], ab + (uint32_t)r * 128u +
                               ((uint32_t)(cc ^ (r & 7)) << 4));
            }
            uint32_t bf[4][4];
            #pragma unroll
            for (int gi = 0; gi < 4; gi++) {
                const int nr = wn0 + gi * 16 + (lane & 7) + ((lane >> 4) << 3);
                const int cc = kk * 2 + ((lane >> 3) & 1);
                ldm_x4(bf[gi], bb + (uint32_t)nr * 128u +
                               ((uint32_t)(cc ^ (nr & 7)) << 4));
            }
            #pragma unroll
            for (int mi = 0; mi < 2; mi++)
                #pragma unroll
                for (int ni = 0; ni < 8; ni++)
                    mma16816(acc[mi][ni], af[mi],
                             bf[ni >> 1][(ni & 1) * 2], bf[ni >> 1][(ni & 1) * 2 + 1]);
        }
    }

    // Epilogue
    const int g = lane >> 2, q = lane & 3;
    #pragma unroll
    for (int mi = 0; mi < 2; mi++) {
        #pragma unroll
        for (int ni = 0; ni < 8; ni++) {
            const int m0 = row0 + wm0 + mi * 16 + g;
            const int cn = col0 + wn0 + ni * 8 + q * 2;
            float v0 = acc[mi][ni][0], v1 = acc[mi][ni][1];
            float v2 = acc[mi][ni][2], v3 = acc[mi][ni][3];
            if (OUT_MODE == 0) {
                __half* Oh = (__half*)outp + zb * sC;
                *(uint32_t*)(Oh + (size_t)m0 * N + cn)       = packh2(v0, v1);
                *(uint32_t*)(Oh + (size_t)(m0 + 8) * N + cn) = packh2(v2, v3);
            } else {
                float* O = (float*)outp + zb * sC;
                const float b0 = bias[cn], b1 = bias[cn + 1];
                *(float2*)(O + (size_t)m0 * N + cn)       = make_float2(v0 + b0, v1 + b1);
                *(float2*)(O + (size_t)(m0 + 8) * N + cn) = make_float2(v2 + b0, v3 + b1);
            }
        }
    }
}

// ---------------------------------------------------------------------------
extern "C" void kernel_launch(void* const* d_in, const int* in_sizes, int n_in,
                              void* d_out, int out_size)
{
    const float* hidden = (const float*)d_in[0];   // [B, S, H]
    const float* mask   = (const float*)d_in[1];   // [B, 1, S, S]
    const float* R      = (const float*)d_in[2];   // [S, S]
    const float* G_w    = (const float*)d_in[3];   // [H, H]
    const float* G_b    = (const float*)d_in[4];   // [H]
    const float* F_w    = (const float*)d_in[5];   // [H, H]
    const float* F_b    = (const float*)d_in[6];   // [H]
    float* out = (float*)d_out;                    // [B, S, H]

    __half *Xh,*Fh,*Gth,*Wh,*Ph,*Th,*Tth;
    float* bias;
    cudaGetSymbolAddress((void**)&Xh,  g_Xh);
    cudaGetSymbolAddress((void**)&Fh,  g_Fh);
    cudaGetSymbolAddress((void**)&Gth, g_Gth);
    cudaGetSymbolAddress((void**)&Wh,  g_Wh);
    cudaGetSymbolAddress((void**)&Ph,  g_Ph);
    cudaGetSymbolAddress((void**)&Th,  g_Th);
    cudaGetSymbolAddress((void**)&Tth, g_Tth);
    cudaGetSymbolAddress((void**)&bias, g_bias);

    cudaFuncSetAttribute((const void*)&hgemm<0>,
                         cudaFuncAttributeMaxDynamicSharedMemorySize, GEMM_SMEM);
    cudaFuncSetAttribute((const void*)&hgemm<1>,
                         cudaFuncAttributeMaxDynamicSharedMemorySize, GEMM_SMEM);

    // Converts (X, F fp16; G transposed fp16)
    conv_kernel<<<MROWS*HDIM/4/256, 256>>>(hidden, Xh, MROWS*HDIM/4);
    conv_kernel<<<HDIM*HDIM/4/256, 256>>>(F_w, Fh, HDIM*HDIM/4);
    tsplit_kernel<<<dim3(HDIM/32, HDIM/32), dim3(32, 8)>>>(G_w, Gth);

    // Softmax -> probs fp16 ; fused bias
    softmax_kernel<<<BATCH*SDIM, 256>>>(R, mask, Ph);
    bias_kernel<<<HDIM, 256>>>(F_w, G_b, F_b, bias);

    // W = Fh @ Gth^T -> fp16
    hgemm<0><<<dim3(8, 8, 1), 256, GEMM_SMEM>>>(
        Fh, Gth, nullptr, Wh, HDIM, HDIM, 0, 0, 0);

    // T = Xh @ Wh^T -> fp16
    hgemm<0><<<dim3(8, 64, 1), 256, GEMM_SMEM>>>(
        Xh, Wh, nullptr, Th, HDIM, HDIM, 0, 0, 0);

    // Transpose T -> per-batch [H, S]
    transpose_kernel<<<dim3(HDIM/32, MROWS/32), dim3(32, 8)>>>(Th, Tth);

    // out = Ph @ Tth^T + bias_total  (batched, fp32 out)
    hgemm<1><<<dim3(8, 16, 4), 256, GEMM_SMEM>>>(
        Ph, Tth, bias, out,
        SDIM, HDIM,
        (long long)SDIM * SDIM, (long long)HDIM * SDIM, (long long)SDIM * HDIM);
}